// round 14
// baseline (speedup 1.0000x reference)
#include <cuda_runtime.h>
#include <cuda_bf16.h>
#include <cstdint>

#define NN 100000
#define NE 1600000
#define CAP 64                // bucket capacity per node (max degree headroom)
#define DIN 256
#define DHID 64
#define DOUT 32

// ---------------- scratch (static device memory: allowed) ----------------
__device__ float  g_x0[NN * DOUT];
__device__ float  g_xa[NN * DOUT];
__device__ float  g_xb[NN * DOUT];
__device__ float2 g_cv[(size_t)NN * CAP];   // bucketed (col-as-int-bits, 0.9*val)
__device__ int    g_deg[NN];

// ---------------- fill: bucketed scatter ----------------
__global__ void k_fill(const int* __restrict__ row, const int* __restrict__ col,
                       const float* __restrict__ val) {
    int e = blockIdx.x * blockDim.x + threadIdx.x;
    if (e < NE) {
        int r = row[e];
        int idx = atomicAdd(&g_deg[r], 1);
        g_cv[(size_t)r * CAP + idx] = make_float2(__int_as_float(col[e]), 0.9f * val[e]);
    }
}

// zero the padding tail (deg .. round8(deg)-1) with (col=0, val=0) sentinels
__global__ void k_pad() {
    int i = blockIdx.x * blockDim.x + threadIdx.x;
    if (i < NN) {
        int d = g_deg[i];
        int dp = (d + 7) & ~7;
        float2* b = &g_cv[(size_t)i * CAP];
        for (int p = d; p < dp; p++) b[p] = make_float2(0.f, 0.f);
    }
}

// ---------------- MLP head: x0 = relu(F@W1 + b1)@W2 + b2 ----------------
// Layer 1 on tf32 tensor cores (mma.sync m16n8k8). Block = 256 thr = 8 warps,
// 128 nodes/block, warp handles an m16 x n64 tile over K=256.
// (UNCHANGED from R12 — measured good)

__device__ __forceinline__ uint32_t f2tf32(float f) {
    uint32_t u;
    asm("cvt.rna.tf32.f32 %0, %1;" : "=r"(u) : "f"(f));
    return u;
}

// smem byte offsets
#define SM_W2    0                       // 64*32 floats  = 8192 B
#define SM_B1    8192                    // 64 floats     = 256 B
#define SM_B2    8448                    // 32 floats     = 128 B
#define SM_BFRAG 8704                    // 8192 uint2    = 65536 B
#define SM_FCH   (8704 + 65536)          // 128*33 uint   = 16896 B
#define SM_HS    8704                    // ALIAS of BFRAG: 128*68 floats = 34816 B
#define SM_TOTAL (SM_FCH + 16896)        // 91136 B

__global__ void __launch_bounds__(256)
k_mlp(const float* __restrict__ features,
      const float* __restrict__ W1, const float* __restrict__ b1,
      const float* __restrict__ W2, const float* __restrict__ b2) {
    extern __shared__ char smraw[];
    float*    w2s   = (float*)(smraw + SM_W2);
    float*    b1s   = (float*)(smraw + SM_B1);
    float*    b2s   = (float*)(smraw + SM_B2);
    uint2*    bfrag = (uint2*)(smraw + SM_BFRAG);
    uint32_t* fch   = (uint32_t*)(smraw + SM_FCH);
    float*    hs    = (float*)(smraw + SM_HS);

    const int tid   = threadIdx.x;
    const int lane  = tid & 31;
    const int wid   = tid >> 5;
    const int node0 = blockIdx.x * 128;

    // fused init for the CSR build that follows
    if (tid < 128 && node0 + tid < NN) g_deg[node0 + tid] = 0;

    // stage W2 / biases
    for (int i = tid; i < DHID * DOUT; i += 256) w2s[i] = W2[i];
    if (tid < DHID) b1s[tid] = b1[tid];
    if (tid < DOUT) b2s[tid] = b2[tid];

    // stage W1 fragment-ordered, tf32-converted
    for (int i = tid; i < 8192; i += 256) {
        int kstep = i >> 8;
        int rem   = i & 255;
        int nt    = rem >> 5;
        int ln    = rem & 31;
        int k     = kstep * 8 + (ln & 3);
        int n     = nt * 8 + (ln >> 2);
        uint32_t t0 = f2tf32(W1[k * DHID + n]);
        uint32_t t1 = f2tf32(W1[(k + 4) * DHID + n]);
        bfrag[i] = make_uint2(t0, t1);
    }
    __syncthreads();

    float c[8][4];
    #pragma unroll
    for (int nt = 0; nt < 8; nt++)
        #pragma unroll
        for (int j = 0; j < 4; j++) c[nt][j] = 0.f;

    const int rw = wid * 16;
    const int r4 = lane >> 2;
    const int q4 = lane & 3;

    for (int ch = 0; ch < 8; ch++) {
        const int k0 = ch * 32;
        __syncthreads();
        #pragma unroll
        for (int r = 0; r < 4; r++) {
            int lin = r * 256 + tid;
            int rowi = lin >> 3;
            int qq   = lin & 7;
            float4 f4 = make_float4(0.f, 0.f, 0.f, 0.f);
            if (node0 + rowi < NN)
                f4 = *(const float4*)&features[(size_t)(node0 + rowi) * DIN + k0 + qq * 4];
            uint32_t* dst = &fch[rowi * 33 + qq * 4];
            dst[0] = f2tf32(f4.x); dst[1] = f2tf32(f4.y);
            dst[2] = f2tf32(f4.z); dst[3] = f2tf32(f4.w);
        }
        __syncthreads();

        #pragma unroll
        for (int kk = 0; kk < 4; kk++) {
            uint32_t a0 = fch[(rw + r4) * 33 + kk * 8 + q4];
            uint32_t a1 = fch[(rw + r4 + 8) * 33 + kk * 8 + q4];
            uint32_t a2 = fch[(rw + r4) * 33 + kk * 8 + q4 + 4];
            uint32_t a3 = fch[(rw + r4 + 8) * 33 + kk * 8 + q4 + 4];
            const int ks = ch * 4 + kk;
            #pragma unroll
            for (int nt = 0; nt < 8; nt++) {
                uint2 bb = bfrag[(ks * 8 + nt) * 32 + lane];
                asm volatile(
                    "mma.sync.aligned.m16n8k8.row.col.f32.tf32.tf32.f32 "
                    "{%0,%1,%2,%3}, {%4,%5,%6,%7}, {%8,%9}, {%0,%1,%2,%3};"
                    : "+f"(c[nt][0]), "+f"(c[nt][1]), "+f"(c[nt][2]), "+f"(c[nt][3])
                    : "r"(a0), "r"(a1), "r"(a2), "r"(a3), "r"(bb.x), "r"(bb.y));
            }
        }
    }

    __syncthreads();   // all bfrag reads done before aliased H stores

    #pragma unroll
    for (int nt = 0; nt < 8; nt++) {
        int col = nt * 8 + 2 * q4;
        float bA = b1s[col], bB = b1s[col + 1];
        float h0 = fmaxf(c[nt][0] + bA, 0.f);
        float h1 = fmaxf(c[nt][1] + bB, 0.f);
        float h2 = fmaxf(c[nt][2] + bA, 0.f);
        float h3 = fmaxf(c[nt][3] + bB, 0.f);
        float2* p0 = (float2*)&hs[(rw + r4) * 68 + col];
        float2* p1 = (float2*)&hs[(rw + r4 + 8) * 68 + col];
        *p0 = make_float2(h0, h1);
        *p1 = make_float2(h2, h3);
    }
    __syncthreads();

    {
        int nodel = tid >> 1;
        int half  = tid & 1;
        int node  = node0 + nodel;
        const float4* hp  = (const float4*)&hs[nodel * 68];
        const float4* w2p = (const float4*)w2s;
        float4 o0 = ((const float4*)b2s)[half * 4 + 0];
        float4 o1 = ((const float4*)b2s)[half * 4 + 1];
        float4 o2 = ((const float4*)b2s)[half * 4 + 2];
        float4 o3 = ((const float4*)b2s)[half * 4 + 3];
        #pragma unroll 4
        for (int k4 = 0; k4 < 16; k4++) {
            float4 h4 = hp[k4];
            float hv[4] = {h4.x, h4.y, h4.z, h4.w};
            #pragma unroll
            for (int s = 0; s < 4; s++) {
                int l = k4 * 4 + s;
                float h = hv[s];
                float4 wv0 = w2p[l * 8 + half * 4 + 0];
                float4 wv1 = w2p[l * 8 + half * 4 + 1];
                float4 wv2 = w2p[l * 8 + half * 4 + 2];
                float4 wv3 = w2p[l * 8 + half * 4 + 3];
                o0.x += h * wv0.x; o0.y += h * wv0.y; o0.z += h * wv0.z; o0.w += h * wv0.w;
                o1.x += h * wv1.x; o1.y += h * wv1.y; o1.z += h * wv1.z; o1.w += h * wv1.w;
                o2.x += h * wv2.x; o2.y += h * wv2.y; o2.z += h * wv2.z; o2.w += h * wv2.w;
                o3.x += h * wv3.x; o3.y += h * wv3.y; o3.z += h * wv3.z; o3.w += h * wv3.w;
            }
        }
        if (node < NN) {
            float4* out = (float4*)&g_x0[(size_t)node * DOUT + half * 16];
            out[0] = o0; out[1] = o1; out[2] = o2; out[3] = o3;
        }
    }
}

// ---------------- propagation: dst = (A' @ src) + 0.1 * x0  (0.9 folded into A') ------
// 4 nodes per warp (same layout as the measured-good R2/R12 kernel).
// ONLY change: trip-paired descriptor loads — descs for trips t and t+1 issue
// back-to-back, so desc latency amortizes 2x and block-1 gathers can issue while
// block-0 FMAs wait on the scoreboard (~16 gathers in flight, +2 regs only).
__global__ void __launch_bounds__(256)
k_spmm(const float* __restrict__ xsrc, float* __restrict__ xdst) {
    int gtid  = blockIdx.x * blockDim.x + threadIdx.x;
    int warp  = gtid >> 5;
    int lane  = threadIdx.x & 31;
    int grp   = lane >> 3;
    int lane8 = lane & 7;
    int node  = warp * 4 + grp;
    if (node >= NN) return;

    int trip = (g_deg[node] + 7) >> 3;
    int mt = trip;
    mt = max(mt, __shfl_xor_sync(0xffffffffu, mt, 16));
    mt = max(mt, __shfl_xor_sync(0xffffffffu, mt, 8));

    const float2* __restrict__ bucket = &g_cv[(size_t)node * CAP];
    int p = lane8;

    float4 acc = make_float4(0.f, 0.f, 0.f, 0.f);
    for (int t = 0; t < mt; t += 2) {
        float2 cv0 = make_float2(0.f, 0.f);
        float2 cv1 = make_float2(0.f, 0.f);
        if (t < trip)     cv0 = __ldg(&bucket[p]);
        if (t + 1 < trip) cv1 = __ldg(&bucket[p + 8]);
        p += 16;
        #pragma unroll
        for (int j = 0; j < 8; j++) {
            int   col = __float_as_int(__shfl_sync(0xffffffffu, cv0.x, (lane & 24) + j));
            float v   = __shfl_sync(0xffffffffu, cv0.y, (lane & 24) + j);
            float4 g = __ldg((const float4*)&xsrc[(size_t)col * DOUT + lane8 * 4]);
            acc.x += v * g.x;
            acc.y += v * g.y;
            acc.z += v * g.z;
            acc.w += v * g.w;
        }
        #pragma unroll
        for (int j = 0; j < 8; j++) {
            int   col = __float_as_int(__shfl_sync(0xffffffffu, cv1.x, (lane & 24) + j));
            float v   = __shfl_sync(0xffffffffu, cv1.y, (lane & 24) + j);
            float4 g = __ldg((const float4*)&xsrc[(size_t)col * DOUT + lane8 * 4]);
            acc.x += v * g.x;
            acc.y += v * g.y;
            acc.z += v * g.z;
            acc.w += v * g.w;
        }
    }

    const float4 x0 = *(const float4*)&g_x0[(size_t)node * DOUT + lane8 * 4];
    float4 o;
    o.x = acc.x + 0.1f * x0.x;
    o.y = acc.y + 0.1f * x0.y;
    o.z = acc.z + 0.1f * x0.z;
    o.w = acc.w + 0.1f * x0.w;
    *(float4*)&xdst[(size_t)node * DOUT + lane8 * 4] = o;
}

// ---------------- launch ----------------
extern "C" void kernel_launch(void* const* d_in, const int* in_sizes, int n_in,
                              void* d_out, int out_size) {
    const float* features = (const float*)d_in[0];
    const int*   row      = (const int*)d_in[1];
    const int*   col      = (const int*)d_in[2];
    const float* vals     = (const float*)d_in[3];
    const float* W1       = (const float*)d_in[4];
    const float* b1       = (const float*)d_in[5];
    const float* W2       = (const float*)d_in[6];
    const float* b2       = (const float*)d_in[7];

    float *x0p, *xap, *xbp;
    cudaGetSymbolAddress((void**)&x0p, g_x0);
    cudaGetSymbolAddress((void**)&xap, g_xa);
    cudaGetSymbolAddress((void**)&xbp, g_xb);

    // 1) MLP head (tf32 tensor cores; also zeroes degree counters)
    cudaFuncSetAttribute(k_mlp, cudaFuncAttributeMaxDynamicSharedMemorySize, SM_TOTAL);
    k_mlp<<<(NN + 127) / 128, 256, SM_TOTAL>>>(features, W1, b1, W2, b2);

    // 2) bucketed CSR build + 3) pad tails to multiple of 8
    k_fill<<<(NE + 255) / 256, 256>>>(row, col, vals);
    k_pad<<<(NN + 255) / 256, 256>>>();

    // 4..13) 10 propagation steps, ping-pong; last writes d_out
    const int spmm_blocks = (NN / 4 * 32 + 255) / 256;   // 4 nodes per warp
    const float* src = x0p;
    for (int it = 0; it < 10; it++) {
        float* dst = (it == 9) ? (float*)d_out : ((it % 2 == 0) ? xap : xbp);
        k_spmm<<<spmm_blocks, 256>>>(src, dst);
        src = dst;
    }
}

// round 15
// speedup vs baseline: 1.1050x; 1.1050x over previous
#include <cuda_runtime.h>
#include <cuda_bf16.h>
#include <cstdint>

#define NN 100000
#define NE 1600000
#define CAP 64                // bucket capacity per node (max degree headroom)
#define DIN 256
#define DHID 64
#define DOUT 32

// ---------------- scratch (static device memory: allowed) ----------------
__device__ float  g_x0[NN * DOUT];
__device__ float  g_xa[NN * DOUT];
__device__ float  g_xb[NN * DOUT];
__device__ float2 g_cv[(size_t)NN * CAP];   // bucketed (col-as-int-bits, 0.9*val)
__device__ int    g_deg[NN];

// ---------------- fill: bucketed scatter ----------------
__global__ void k_fill(const int* __restrict__ row, const int* __restrict__ col,
                       const float* __restrict__ val) {
    int e = blockIdx.x * blockDim.x + threadIdx.x;
    if (e < NE) {
        int r = row[e];
        int idx = atomicAdd(&g_deg[r], 1);
        g_cv[(size_t)r * CAP + idx] = make_float2(__int_as_float(col[e]), 0.9f * val[e]);
    }
}

// zero the padding tail (deg .. round8(deg)-1) with (col=0, val=0) sentinels
__global__ void k_pad() {
    int i = blockIdx.x * blockDim.x + threadIdx.x;
    if (i < NN) {
        int d = g_deg[i];
        int dp = (d + 7) & ~7;
        float2* b = &g_cv[(size_t)i * CAP];
        for (int p = d; p < dp; p++) b[p] = make_float2(0.f, 0.f);
    }
}

// ---------------- MLP head: x0 = relu(F@W1 + b1)@W2 + b2 ----------------
// Layer 1 on tf32 tensor cores (mma.sync m16n8k8). UNCHANGED from the 346us build.

__device__ __forceinline__ uint32_t f2tf32(float f) {
    uint32_t u;
    asm("cvt.rna.tf32.f32 %0, %1;" : "=r"(u) : "f"(f));
    return u;
}

// smem byte offsets
#define SM_W2    0                       // 64*32 floats  = 8192 B
#define SM_B1    8192                    // 64 floats     = 256 B
#define SM_B2    8448                    // 32 floats     = 128 B
#define SM_BFRAG 8704                    // 8192 uint2    = 65536 B
#define SM_FCH   (8704 + 65536)          // 128*33 uint   = 16896 B
#define SM_HS    8704                    // ALIAS of BFRAG: 128*68 floats = 34816 B
#define SM_TOTAL (SM_FCH + 16896)        // 91136 B

__global__ void __launch_bounds__(256)
k_mlp(const float* __restrict__ features,
      const float* __restrict__ W1, const float* __restrict__ b1,
      const float* __restrict__ W2, const float* __restrict__ b2) {
    extern __shared__ char smraw[];
    float*    w2s   = (float*)(smraw + SM_W2);
    float*    b1s   = (float*)(smraw + SM_B1);
    float*    b2s   = (float*)(smraw + SM_B2);
    uint2*    bfrag = (uint2*)(smraw + SM_BFRAG);
    uint32_t* fch   = (uint32_t*)(smraw + SM_FCH);
    float*    hs    = (float*)(smraw + SM_HS);

    const int tid   = threadIdx.x;
    const int lane  = tid & 31;
    const int wid   = tid >> 5;
    const int node0 = blockIdx.x * 128;

    // fused init for the CSR build that follows
    if (tid < 128 && node0 + tid < NN) g_deg[node0 + tid] = 0;

    // stage W2 / biases
    for (int i = tid; i < DHID * DOUT; i += 256) w2s[i] = W2[i];
    if (tid < DHID) b1s[tid] = b1[tid];
    if (tid < DOUT) b2s[tid] = b2[tid];

    // stage W1 fragment-ordered, tf32-converted
    for (int i = tid; i < 8192; i += 256) {
        int kstep = i >> 8;
        int rem   = i & 255;
        int nt    = rem >> 5;
        int ln    = rem & 31;
        int k     = kstep * 8 + (ln & 3);
        int n     = nt * 8 + (ln >> 2);
        uint32_t t0 = f2tf32(W1[k * DHID + n]);
        uint32_t t1 = f2tf32(W1[(k + 4) * DHID + n]);
        bfrag[i] = make_uint2(t0, t1);
    }
    __syncthreads();

    float c[8][4];
    #pragma unroll
    for (int nt = 0; nt < 8; nt++)
        #pragma unroll
        for (int j = 0; j < 4; j++) c[nt][j] = 0.f;

    const int rw = wid * 16;
    const int r4 = lane >> 2;
    const int q4 = lane & 3;

    for (int ch = 0; ch < 8; ch++) {
        const int k0 = ch * 32;
        __syncthreads();
        #pragma unroll
        for (int r = 0; r < 4; r++) {
            int lin = r * 256 + tid;
            int rowi = lin >> 3;
            int qq   = lin & 7;
            float4 f4 = make_float4(0.f, 0.f, 0.f, 0.f);
            if (node0 + rowi < NN)
                f4 = *(const float4*)&features[(size_t)(node0 + rowi) * DIN + k0 + qq * 4];
            uint32_t* dst = &fch[rowi * 33 + qq * 4];
            dst[0] = f2tf32(f4.x); dst[1] = f2tf32(f4.y);
            dst[2] = f2tf32(f4.z); dst[3] = f2tf32(f4.w);
        }
        __syncthreads();

        #pragma unroll
        for (int kk = 0; kk < 4; kk++) {
            uint32_t a0 = fch[(rw + r4) * 33 + kk * 8 + q4];
            uint32_t a1 = fch[(rw + r4 + 8) * 33 + kk * 8 + q4];
            uint32_t a2 = fch[(rw + r4) * 33 + kk * 8 + q4 + 4];
            uint32_t a3 = fch[(rw + r4 + 8) * 33 + kk * 8 + q4 + 4];
            const int ks = ch * 4 + kk;
            #pragma unroll
            for (int nt = 0; nt < 8; nt++) {
                uint2 bb = bfrag[(ks * 8 + nt) * 32 + lane];
                asm volatile(
                    "mma.sync.aligned.m16n8k8.row.col.f32.tf32.tf32.f32 "
                    "{%0,%1,%2,%3}, {%4,%5,%6,%7}, {%8,%9}, {%0,%1,%2,%3};"
                    : "+f"(c[nt][0]), "+f"(c[nt][1]), "+f"(c[nt][2]), "+f"(c[nt][3])
                    : "r"(a0), "r"(a1), "r"(a2), "r"(a3), "r"(bb.x), "r"(bb.y));
            }
        }
    }

    __syncthreads();   // all bfrag reads done before aliased H stores

    #pragma unroll
    for (int nt = 0; nt < 8; nt++) {
        int col = nt * 8 + 2 * q4;
        float bA = b1s[col], bB = b1s[col + 1];
        float h0 = fmaxf(c[nt][0] + bA, 0.f);
        float h1 = fmaxf(c[nt][1] + bB, 0.f);
        float h2 = fmaxf(c[nt][2] + bA, 0.f);
        float h3 = fmaxf(c[nt][3] + bB, 0.f);
        float2* p0 = (float2*)&hs[(rw + r4) * 68 + col];
        float2* p1 = (float2*)&hs[(rw + r4 + 8) * 68 + col];
        *p0 = make_float2(h0, h1);
        *p1 = make_float2(h2, h3);
    }
    __syncthreads();

    {
        int nodel = tid >> 1;
        int half  = tid & 1;
        int node  = node0 + nodel;
        const float4* hp  = (const float4*)&hs[nodel * 68];
        const float4* w2p = (const float4*)w2s;
        float4 o0 = ((const float4*)b2s)[half * 4 + 0];
        float4 o1 = ((const float4*)b2s)[half * 4 + 1];
        float4 o2 = ((const float4*)b2s)[half * 4 + 2];
        float4 o3 = ((const float4*)b2s)[half * 4 + 3];
        #pragma unroll 4
        for (int k4 = 0; k4 < 16; k4++) {
            float4 h4 = hp[k4];
            float hv[4] = {h4.x, h4.y, h4.z, h4.w};
            #pragma unroll
            for (int s = 0; s < 4; s++) {
                int l = k4 * 4 + s;
                float h = hv[s];
                float4 wv0 = w2p[l * 8 + half * 4 + 0];
                float4 wv1 = w2p[l * 8 + half * 4 + 1];
                float4 wv2 = w2p[l * 8 + half * 4 + 2];
                float4 wv3 = w2p[l * 8 + half * 4 + 3];
                o0.x += h * wv0.x; o0.y += h * wv0.y; o0.z += h * wv0.z; o0.w += h * wv0.w;
                o1.x += h * wv1.x; o1.y += h * wv1.y; o1.z += h * wv1.z; o1.w += h * wv1.w;
                o2.x += h * wv2.x; o2.y += h * wv2.y; o2.z += h * wv2.z; o2.w += h * wv2.w;
                o3.x += h * wv3.x; o3.y += h * wv3.y; o3.z += h * wv3.z; o3.w += h * wv3.w;
            }
        }
        if (node < NN) {
            float4* out = (float4*)&g_x0[(size_t)node * DOUT + half * 16];
            out[0] = o0; out[1] = o1; out[2] = o2; out[3] = o3;
        }
    }
}

// ---------------- propagation: dst = (A' @ src) + 0.1 * x0  (0.9 folded into A') ------
// 4 nodes per warp. ONLY change vs the 346us build: per-GROUP trip loop.
// The inner shuffles only source lanes inside the 8-lane group, so each group
// runs its exact ceil(deg/8) trips under an 8-lane mask instead of the warp
// taking max over 4 nodes — removes ~18% of gather wavefronts (the quad-max
// sentinel waste) plus the max-reduction and per-trip guard.
__global__ void __launch_bounds__(256)
k_spmm(const float* __restrict__ xsrc, float* __restrict__ xdst) {
    int gtid  = blockIdx.x * blockDim.x + threadIdx.x;
    int warp  = gtid >> 5;
    int lane  = threadIdx.x & 31;
    int grp8  = lane & 24;               // group base lane (0,8,16,24)
    int lane8 = lane & 7;
    int node  = warp * 4 + (lane >> 3);  // 25000 warps exactly cover NN
    unsigned gmask = 0xFFu << grp8;      // this group's shuffle mask

    int trip = (g_deg[node] + 7) >> 3;   // exact trips for THIS node

    const float2* __restrict__ bucket = &g_cv[(size_t)node * CAP];
    int p = lane8;

    float4 acc = make_float4(0.f, 0.f, 0.f, 0.f);
    for (int t = 0; t < trip; t++) {
        float2 cv = __ldg(&bucket[p]);   // always valid: bucket padded to 8
        p += 8;
        #pragma unroll
        for (int j = 0; j < 8; j++) {
            int   col = __float_as_int(__shfl_sync(gmask, cv.x, grp8 + j));
            float v   = __shfl_sync(gmask, cv.y, grp8 + j);
            float4 g = __ldg((const float4*)&xsrc[(size_t)col * DOUT + lane8 * 4]);
            acc.x += v * g.x;
            acc.y += v * g.y;
            acc.z += v * g.z;
            acc.w += v * g.w;
        }
    }

    const float4 x0 = *(const float4*)&g_x0[(size_t)node * DOUT + lane8 * 4];
    float4 o;
    o.x = acc.x + 0.1f * x0.x;
    o.y = acc.y + 0.1f * x0.y;
    o.z = acc.z + 0.1f * x0.z;
    o.w = acc.w + 0.1f * x0.w;
    *(float4*)&xdst[(size_t)node * DOUT + lane8 * 4] = o;
}

// ---------------- launch ----------------
extern "C" void kernel_launch(void* const* d_in, const int* in_sizes, int n_in,
                              void* d_out, int out_size) {
    const float* features = (const float*)d_in[0];
    const int*   row      = (const int*)d_in[1];
    const int*   col      = (const int*)d_in[2];
    const float* vals     = (const float*)d_in[3];
    const float* W1       = (const float*)d_in[4];
    const float* b1       = (const float*)d_in[5];
    const float* W2       = (const float*)d_in[6];
    const float* b2       = (const float*)d_in[7];

    float *x0p, *xap, *xbp;
    cudaGetSymbolAddress((void**)&x0p, g_x0);
    cudaGetSymbolAddress((void**)&xap, g_xa);
    cudaGetSymbolAddress((void**)&xbp, g_xb);

    // 1) MLP head (tf32 tensor cores; also zeroes degree counters)
    cudaFuncSetAttribute(k_mlp, cudaFuncAttributeMaxDynamicSharedMemorySize, SM_TOTAL);
    k_mlp<<<(NN + 127) / 128, 256, SM_TOTAL>>>(features, W1, b1, W2, b2);

    // 2) bucketed CSR build + 3) pad tails to multiple of 8
    k_fill<<<(NE + 255) / 256, 256>>>(row, col, vals);
    k_pad<<<(NN + 255) / 256, 256>>>();

    // 4..13) 10 propagation steps, ping-pong; last writes d_out
    const int spmm_blocks = (NN / 4 * 32 + 255) / 256;   // 4 nodes per warp
    const float* src = x0p;
    for (int it = 0; it < 10; it++) {
        float* dst = (it == 9) ? (float*)d_out : ((it % 2 == 0) ? xap : xbp);
        k_spmm<<<spmm_blocks, 256>>>(src, dst);
        src = dst;
    }
}